// round 10
// baseline (speedup 1.0000x reference)
#include <cuda_runtime.h>
#include <cstdint>

#define D_MODEL 2048
#define D_FF    4096
#define NEXP    8
#define NTOK    2048
#define NPAIR   (NTOK * 2)
#define ALPHA   0.01f
#define BK      32

// GEMM1 stage layout (ring 2): A planes 12288, f32 staging 16384, B planes 9216
#define A_OFF   0
#define ST_OFF  12288
#define B_OFF   28672
#define ST_SZ   37888
#define SMEM1_BYTES (2 * ST_SZ)      // 75776

// GEMM2 stage layout (ring 2): A planes 12288, f32 staging 8192, B planes 4608
#define ST2_OFF 12288
#define B2_OFF  20480
#define ST2_SZ  25088
#define SMEM2_BYTES (2 * ST2_SZ)     // 50176

// dequant constants
#define C1_G1  6.103515625e-5f        // 2^14 / (2^11 * 2^17)
#define C2_G1  4.76837158203125e-7f   // 2^7  / 2^28
#define C1_G2  1.220703125e-4f        // 2^14 / (2^10 * 2^17)
#define C2_G2  9.5367431640625e-7f    // 2^7  / 2^27
#define C3_G2  7.450580596923828e-9f  // 2^0  / 2^27

// ---------------- scratch ----------------
__device__ __align__(256) signed char g_xhi[(size_t)NTOK * D_MODEL];
__device__ __align__(256) signed char g_xlo[(size_t)NTOK * D_MODEL];
__device__ __align__(256) signed char g_Hhi[(size_t)NPAIR * D_FF];
__device__ __align__(256) signed char g_Hlo[(size_t)NPAIR * D_FF];
__device__ float g_probs[NTOK * NEXP];
__device__ int   g_sel_e[NTOK * 2];
__device__ float g_sel_w[NTOK * 2];
__device__ int   g_counts[NEXP];
__device__ int   g_offsets[NEXP + 1];
__device__ int   g_cursor[NEXP];
__device__ int   g_pair_token[NPAIR];
__device__ float g_pair_w[NPAIR];

// ---------------- helpers ----------------
__device__ __forceinline__ void mma_s8(int c[4], const uint32_t a[4], const uint32_t b[2]) {
    asm volatile(
        "mma.sync.aligned.m16n8k32.row.col.s32.s8.s8.s32 "
        "{%0,%1,%2,%3}, {%4,%5,%6,%7}, {%8,%9}, {%0,%1,%2,%3};"
        : "+r"(c[0]), "+r"(c[1]), "+r"(c[2]), "+r"(c[3])
        : "r"(a[0]), "r"(a[1]), "r"(a[2]), "r"(a[3]), "r"(b[0]), "r"(b[1]));
}
__device__ __forceinline__ void ldsm4(uint32_t* r, uint32_t addr) {
    asm volatile("ldmatrix.sync.aligned.m8n8.x4.shared.b16 {%0,%1,%2,%3}, [%4];"
                 : "=r"(r[0]), "=r"(r[1]), "=r"(r[2]), "=r"(r[3]) : "r"(addr));
}
__device__ __forceinline__ uint32_t lds32(uint32_t addr) {
    uint32_t v;
    asm volatile("ld.shared.b32 %0, [%1];" : "=r"(v) : "r"(addr));
    return v;
}
__device__ __forceinline__ void cp_async16(uint32_t dst, const void* src, int bytes) {
    asm volatile("cp.async.cg.shared.global [%0], [%1], 16, %2;\n"
                 :: "r"(dst), "l"(src), "r"(bytes));
}
__device__ __forceinline__ void cp_commit() { asm volatile("cp.async.commit_group;\n"); }
template<int N> __device__ __forceinline__ void cp_wait() {
    asm volatile("cp.async.wait_group %0;\n" :: "n"(N));
}
__device__ __forceinline__ void quant_split(float v, float S, int& hi, int& lo) {
    int q = __float2int_rn(v * S);
    q = max(-16256, min(16256, q));
    hi = (q + 64) >> 7;
    lo = q - (hi << 7);
}

// ---------------- kernel 0: zero out + counts, quantize x ----------------
__global__ void prep_kernel(const float* __restrict__ x, float* __restrict__ out) {
    int i = blockIdx.x * blockDim.x + threadIdx.x;
    if (i < NEXP) g_counts[i] = 0;
    const float4* x4 = (const float4*)x;
    float4* o4 = (float4*)out;
    float4 z = make_float4(0.f, 0.f, 0.f, 0.f);
    for (int j = i; j < NTOK * D_MODEL / 4; j += gridDim.x * blockDim.x) {
        float4 v = x4[j];
        int h0, l0, h1, l1, h2, l2, h3, l3;
        quant_split(v.x, 2048.f, h0, l0);
        quant_split(v.y, 2048.f, h1, l1);
        quant_split(v.z, 2048.f, h2, l2);
        quant_split(v.w, 2048.f, h3, l3);
        *(char4*)(g_xhi + (size_t)j * 4) = make_char4((char)h0, (char)h1, (char)h2, (char)h3);
        *(char4*)(g_xlo + (size_t)j * 4) = make_char4((char)l0, (char)l1, (char)l2, (char)l3);
        o4[j] = z;
    }
}

// ---------------- kernel 1: router ----------------
__global__ void router_kernel(const float* __restrict__ x, const float* __restrict__ Wr) {
    int t = blockIdx.x;
    int wid = threadIdx.x >> 5, lane = threadIdx.x & 31;
    const float4* xr = (const float4*)(x + (size_t)t * D_MODEL);
    const float4* wr = (const float4*)(Wr + (size_t)wid * D_MODEL);
    float s = 0.0f;
    for (int i = lane; i < D_MODEL / 4; i += 32) {
        float4 a = xr[i], b = wr[i];
        s += a.x * b.x + a.y * b.y + a.z * b.z + a.w * b.w;
    }
    #pragma unroll
    for (int o = 16; o; o >>= 1) s += __shfl_xor_sync(0xFFFFFFFFu, s, o);
    __shared__ float logits[NEXP];
    if (lane == 0) logits[wid] = s;
    __syncthreads();
    if (threadIdx.x == 0) {
        float mx = -1e30f;
        #pragma unroll
        for (int e = 0; e < NEXP; e++) mx = fmaxf(mx, logits[e]);
        float p[NEXP], sum = 0.0f;
        #pragma unroll
        for (int e = 0; e < NEXP; e++) { p[e] = expf(logits[e] - mx); sum += p[e]; }
        float inv = 1.0f / sum;
        #pragma unroll
        for (int e = 0; e < NEXP; e++) { p[e] *= inv; g_probs[t * NEXP + e] = p[e]; }
        int e0 = 0; float p0 = p[0];
        #pragma unroll
        for (int e = 1; e < NEXP; e++) if (p[e] > p0) { p0 = p[e]; e0 = e; }
        int e1 = -1; float p1 = -1.0f;
        #pragma unroll
        for (int e = 0; e < NEXP; e++) if (e != e0 && p[e] > p1) { p1 = p[e]; e1 = e; }
        float ws = p0 + p1;
        g_sel_e[t * 2 + 0] = e0; g_sel_w[t * 2 + 0] = p0 / ws;
        g_sel_e[t * 2 + 1] = e1; g_sel_w[t * 2 + 1] = p1 / ws;
        atomicAdd(&g_counts[e0], 1);
        atomicAdd(&g_counts[e1], 1);
    }
}

__global__ void scan_kernel() {
    if (threadIdx.x == 0) {
        int acc = 0; g_offsets[0] = 0;
        for (int e = 0; e < NEXP; e++) { acc += g_counts[e]; g_offsets[e + 1] = acc; g_cursor[e] = 0; }
    }
}

__global__ void scatter_kernel() {
    int t = blockIdx.x * blockDim.x + threadIdx.x;
    if (t >= NTOK) return;
    #pragma unroll
    for (int k = 0; k < 2; k++) {
        int e = g_sel_e[t * 2 + k];
        int pos = g_offsets[e] + atomicAdd(&g_cursor[e], 1);
        g_pair_token[pos] = t;
        g_pair_w[pos] = g_sel_w[t * 2 + k];
    }
}

// =======================================================================
// GEMM1 (int8 split, 3-mma): H = silu(x@W1)*(x@W3). BM=128 BN=64 BK=32.
// =======================================================================
__global__ void __launch_bounds__(256) gemm1_kernel(
    const float* __restrict__ W1, const float* __restrict__ W3)
{
    extern __shared__ char smem[];
    uint32_t sb = (uint32_t)__cvta_generic_to_shared(smem);

    int e = blockIdx.z;
    int seg0 = g_offsets[e], seg1 = g_offsets[e + 1];
    int m_start = seg0 + blockIdx.x * 128;
    if (m_start >= seg1) return;
    int rows = seg1 - m_start;
    if (rows > 128) rows = 128;
    int n0 = blockIdx.y * 64;

    int tid = threadIdx.x;
    int wid = tid >> 5, lane = tid & 31;
    int wm = wid & 3, wn = wid >> 2;
    int g = lane >> 2, tg = lane & 3;

    const signed char* a_src[2]; uint32_t a_dst[2]; int a_by[2];
    #pragma unroll
    for (int j = 0; j < 2; j++) {
        int idx = tid + 256 * j;
        int r = idx >> 2, sub = idx & 3;
        int plane = sub >> 1, c = sub & 1;
        int tok = (r < rows) ? g_pair_token[m_start + r] : 0;
        a_src[j] = (plane ? g_xlo : g_xhi) + (size_t)tok * D_MODEL + c * 16;
        a_by[j] = (r < rows) ? 16 : 0;
        a_dst[j] = (uint32_t)(A_OFF + plane * 6144 + r * 48 + c * 16);
    }
    const float* st_src[4]; uint32_t st_dst[4];
    #pragma unroll
    for (int j = 0; j < 4; j++) {
        int idx = tid + 256 * j;
        int mat = idx >> 9, rem = idx & 511;
        int r = rem >> 4, c = rem & 15;
        const float* W = mat ? W3 : W1;
        st_src[j] = W + ((size_t)e * D_MODEL + r) * D_FF + n0 + c * 4;
        st_dst[j] = (uint32_t)(ST_OFF + mat * 8192 + r * 256 + c * 16);
    }

    #define LOAD1(s, kt) do {                                                     \
        uint32_t so_ = sb + (uint32_t)(s) * ST_SZ;                                 \
        int k0_ = (kt) * BK;                                                       \
        _Pragma("unroll")                                                          \
        for (int j = 0; j < 2; j++) cp_async16(so_ + a_dst[j], a_src[j] + k0_, a_by[j]); \
        _Pragma("unroll")                                                          \
        for (int j = 0; j < 4; j++) cp_async16(so_ + st_dst[j], st_src[j] + (size_t)k0_ * D_FF, 16); \
    } while (0)

    int cv_mat = tid >> 7, cv_u = tid & 127;
    int cv_kq = cv_u >> 4, cv_nq = cv_u & 15;

    #define CONVERT1(s) do {                                                       \
        const float* stp = (const float*)(smem + (s) * ST_SZ + ST_OFF + cv_mat * 8192) \
                         + cv_kq * 4 * 64 + cv_nq * 4;                             \
        int hi_[4][4], lo_[4][4];                                                  \
        _Pragma("unroll")                                                          \
        for (int j = 0; j < 4; j++) {                                              \
            float4 v = *(const float4*)(stp + j * 64);                             \
            quant_split(v.x, 131072.f, hi_[j][0], lo_[j][0]);                      \
            quant_split(v.y, 131072.f, hi_[j][1], lo_[j][1]);                      \
            quant_split(v.z, 131072.f, hi_[j][2], lo_[j][2]);                      \
            quant_split(v.w, 131072.f, hi_[j][3], lo_[j][3]);                      \
        }                                                                          \
        char* bpl = smem + (s) * ST_SZ + B_OFF + cv_mat * 4608;                    \
        _Pragma("unroll")                                                          \
        for (int nn = 0; nn < 4; nn++) {                                           \
            int n = cv_nq * 4 + nn, T = n >> 3, nin = n & 7;                       \
            uint32_t hw = (hi_[0][nn] & 0xFF) | ((hi_[1][nn] & 0xFF) << 8)         \
                        | ((hi_[2][nn] & 0xFF) << 16) | ((hi_[3][nn] & 0xFF) << 24); \
            uint32_t lw = (lo_[0][nn] & 0xFF) | ((lo_[1][nn] & 0xFF) << 8)         \
                        | ((lo_[2][nn] & 0xFF) << 16) | ((lo_[3][nn] & 0xFF) << 24); \
            *(uint32_t*)(bpl + T * 288 + cv_kq * 32 + nin * 4) = hw;               \
            *(uint32_t*)(bpl + 2304 + T * 288 + cv_kq * 32 + nin * 4) = lw;        \
        }                                                                          \
    } while (0)

    int lr = lane & 7, lrow8 = ((lane >> 3) & 1) * 8, lch = ((lane >> 4) & 1) * 16;
    uint32_t aRel[2][2];
    #pragma unroll
    for (int p = 0; p < 2; p++)
        #pragma unroll
        for (int mi = 0; mi < 2; mi++)
            aRel[p][mi] = (uint32_t)(A_OFF + p * 6144 + (wm * 32 + mi * 16 + lr + lrow8) * 48 + lch);
    uint32_t bRel = (uint32_t)(tg * 32 + g * 4);

    int hh[2][2][4][4] = {};
    int mm[2][2][4][4] = {};

    const int KT = D_MODEL / BK;

    LOAD1(0, 0); cp_commit();

    for (int i = 0; i < KT; i++) {
        int s = i & 1;
        uint32_t so32 = sb + (uint32_t)s * ST_SZ;

        cp_wait<0>();
        __syncthreads();
        if (i + 1 < KT) { LOAD1(s ^ 1, i + 1); cp_commit(); }
        CONVERT1(s);
        __syncthreads();

        uint32_t ah[2][4], al[2][4];
        #pragma unroll
        for (int mi = 0; mi < 2; mi++) {
            ldsm4(ah[mi], so32 + aRel[0][mi]);
            ldsm4(al[mi], so32 + aRel[1][mi]);
        }
        #pragma unroll
        for (int mat = 0; mat < 2; mat++) {
            uint32_t bh[4][2], bl[4][2];
            #pragma unroll
            for (int ni = 0; ni < 4; ni++) {
                uint32_t base = so32 + B_OFF + mat * 4608 + (wn * 4 + ni) * 288 + bRel;
                bh[ni][0] = lds32(base);        bh[ni][1] = lds32(base + 128);
                bl[ni][0] = lds32(base + 2304); bl[ni][1] = lds32(base + 2304 + 128);
            }
            #pragma unroll
            for (int mi = 0; mi < 2; mi++)
                #pragma unroll
                for (int ni = 0; ni < 4; ni++) {
                    mma_s8(hh[mat][mi][ni], ah[mi], bh[ni]);
                    mma_s8(mm[mat][mi][ni], ah[mi], bl[ni]);
                    mma_s8(mm[mat][mi][ni], al[mi], bh[ni]);
                }
        }
    }

    // epilogue: dequant, SwiGLU, quantize H to int8 hi/lo planes
    #pragma unroll
    for (int mi = 0; mi < 2; mi++) {
        int r0 = wm * 32 + mi * 16 + g;
        #pragma unroll
        for (int ni = 0; ni < 4; ni++) {
            int c0 = n0 + wn * 32 + ni * 8 + 2 * tg;
            #pragma unroll
            for (int half = 0; half < 2; half++) {
                int r = r0 + half * 8;
                if (r >= rows) continue;
                size_t rowoff = (size_t)(m_start + r) * D_FF + c0;
                int hA[2], lA[2];
                #pragma unroll
                for (int cc = 0; cc < 2; cc++) {
                    int ci = half * 2 + cc;
                    float gate = C1_G1 * (float)hh[0][mi][ni][ci] + C2_G1 * (float)mm[0][mi][ni][ci];
                    float up   = C1_G1 * (float)hh[1][mi][ni][ci] + C2_G1 * (float)mm[1][mi][ni][ci];
                    float h = gate * up / (1.0f + expf(-gate));
                    quant_split(h, 1024.f, hA[cc], lA[cc]);
                }
                *(char2*)(g_Hhi + rowoff) = make_char2((char)hA[0], (char)hA[1]);
                *(char2*)(g_Hlo + rowoff) = make_char2((char)lA[0], (char)lA[1]);
            }
        }
    }
    #undef LOAD1
    #undef CONVERT1
}

// =======================================================================
// GEMM2 (int8 split, 4-mma EXACT): out += w*(H@W2). BM=128 BN=64 BK=32.
// Adds ll accumulator (lo*lo) -> integer-exact product of quantized operands.
// =======================================================================
__global__ void __launch_bounds__(256) gemm2_kernel(
    const float* __restrict__ W2, float* __restrict__ out)
{
    extern __shared__ char smem[];
    uint32_t sb = (uint32_t)__cvta_generic_to_shared(smem);

    int e = blockIdx.z;
    int seg0 = g_offsets[e], seg1 = g_offsets[e + 1];
    int m_start = seg0 + blockIdx.x * 128;
    if (m_start >= seg1) return;
    int rows = seg1 - m_start;
    if (rows > 128) rows = 128;
    int n0 = blockIdx.y * 64;

    int tid = threadIdx.x;
    int wid = tid >> 5, lane = tid & 31;
    int wm = wid & 3, wn = wid >> 2;     // warp tile 32m x 32n
    int g = lane >> 2, tg = lane & 3;

    const signed char* a_src[2]; uint32_t a_dst[2]; int a_by[2];
    #pragma unroll
    for (int j = 0; j < 2; j++) {
        int idx = tid + 256 * j;
        int r = idx >> 2, sub = idx & 3;
        int plane = sub >> 1, c = sub & 1;
        int pr = (r < rows) ? (m_start + r) : m_start;
        a_src[j] = (plane ? g_Hlo : g_Hhi) + (size_t)pr * D_FF + c * 16;
        a_by[j] = (r < rows) ? 16 : 0;
        a_dst[j] = (uint32_t)(A_OFF + plane * 6144 + r * 48 + c * 16);
    }
    // staging loader: 512 chunks (32k x 16c), 2/thread
    const float* st_src[2]; uint32_t st_dst[2];
    #pragma unroll
    for (int j = 0; j < 2; j++) {
        int idx = tid + 256 * j;
        int r = idx >> 4, c = idx & 15;
        st_src[j] = W2 + ((size_t)e * D_FF + r) * D_MODEL + n0 + c * 4;
        st_dst[j] = (uint32_t)(ST2_OFF + r * 256 + c * 16);
    }

    #define LOAD2(s, kt) do {                                                     \
        uint32_t so_ = sb + (uint32_t)(s) * ST2_SZ;                                \
        int k0_ = (kt) * BK;                                                       \
        _Pragma("unroll")                                                          \
        for (int j = 0; j < 2; j++) cp_async16(so_ + a_dst[j], a_src[j] + k0_, a_by[j]); \
        _Pragma("unroll")                                                          \
        for (int j = 0; j < 2; j++) cp_async16(so_ + st_dst[j], st_src[j] + (size_t)k0_ * D_MODEL, 16); \
    } while (0)

    // convert: 128 active threads, each 4k x 4n (8 kq x 16 nq)
    int cv_kq = (tid & 127) >> 4, cv_nq = tid & 15;

    #define CONVERT2(s) do {                                                       \
        const float* stp = (const float*)(smem + (s) * ST2_SZ + ST2_OFF)           \
                         + cv_kq * 4 * 64 + cv_nq * 4;                             \
        int hi_[4][4], lo_[4][4];                                                  \
        _Pragma("unroll")                                                          \
        for (int j = 0; j < 4; j++) {                                              \
            float4 v = *(const float4*)(stp + j * 64);                             \
            quant_split(v.x, 131072.f, hi_[j][0], lo_[j][0]);                      \
            quant_split(v.y, 131072.f, hi_[j][1], lo_[j][1]);                      \
            quant_split(v.z, 131072.f, hi_[j][2], lo_[j][2]);                      \
            quant_split(v.w, 131072.f, hi_[j][3], lo_[j][3]);                      \
        }                                                                          \
        char* bpl = smem + (s) * ST2_SZ + B2_OFF;                                  \
        _Pragma("unroll")                                                          \
        for (int nn = 0; nn < 4; nn++) {                                           \
            int n = cv_nq * 4 + nn, T = n >> 3, nin = n & 7;                       \
            uint32_t hw = (hi_[0][nn] & 0xFF) | ((hi_[1][nn] & 0xFF) << 8)         \
                        | ((hi_[2][nn] & 0xFF) << 16) | ((hi_[3][nn] & 0xFF) << 24); \
            uint32_t lw = (lo_[0][nn] & 0xFF) | ((lo_[1][nn] & 0xFF) << 8)         \
                        | ((lo_[2][nn] & 0xFF) << 16) | ((lo_[3][nn] & 0xFF) << 24); \
            *(uint32_t*)(bpl + T * 288 + cv_kq * 32 + nin * 4) = hw;               \
            *(uint32_t*)(bpl + 2304 + T * 288 + cv_kq * 32 + nin * 4) = lw;        \
        }                                                                          \
    } while (0)

    int lr = lane & 7, lrow8 = ((lane >> 3) & 1) * 8, lch = ((lane >> 4) & 1) * 16;
    uint32_t aRel[2][2];
    #pragma unroll
    for (int p = 0; p < 2; p++)
        #pragma unroll
        for (int mi = 0; mi < 2; mi++)
            aRel[p][mi] = (uint32_t)(A_OFF + p * 6144 + (wm * 32 + mi * 16 + lr + lrow8) * 48 + lch);
    uint32_t bRel = (uint32_t)(tg * 32 + g * 4);

    int hh[2][4][4] = {};   // [mi][ni][4]
    int mm[2][4][4] = {};
    int ll[2][4][4] = {};

    const int KT = D_FF / BK;

    LOAD2(0, 0); cp_commit();

    for (int i = 0; i < KT; i++) {
        int s = i & 1;
        uint32_t so32 = sb + (uint32_t)s * ST2_SZ;

        cp_wait<0>();
        __syncthreads();
        if (i + 1 < KT) { LOAD2(s ^ 1, i + 1); cp_commit(); }
        if (tid < 128) CONVERT2(s);
        __syncthreads();

        uint32_t ah[2][4], al[2][4];
        #pragma unroll
        for (int mi = 0; mi < 2; mi++) {
            ldsm4(ah[mi], so32 + aRel[0][mi]);
            ldsm4(al[mi], so32 + aRel[1][mi]);
        }
        #pragma unroll
        for (int ni = 0; ni < 4; ni++) {
            uint32_t base = so32 + B2_OFF + (wn * 4 + ni) * 288 + bRel;
            uint32_t bh[2], bl[2];
            bh[0] = lds32(base);        bh[1] = lds32(base + 128);
            bl[0] = lds32(base + 2304); bl[1] = lds32(base + 2304 + 128);
            #pragma unroll
            for (int mi = 0; mi < 2; mi++) {
                mma_s8(hh[mi][ni], ah[mi], bh);
                mma_s8(mm[mi][ni], ah[mi], bl);
                mma_s8(mm[mi][ni], al[mi], bh);
                mma_s8(ll[mi][ni], al[mi], bl);
            }
        }
    }

    // epilogue: exact dequant + weighted atomic scatter (2 adds/element -> deterministic)
    #pragma unroll
    for (int mi = 0; mi < 2; mi++) {
        int r0 = wm * 32 + mi * 16 + g;
        int tokA = -1, tokB = -1;
        float wA = 0.f, wB = 0.f;
        if (r0 < rows)     { tokA = g_pair_token[m_start + r0];     wA = g_pair_w[m_start + r0]; }
        if (r0 + 8 < rows) { tokB = g_pair_token[m_start + r0 + 8]; wB = g_pair_w[m_start + r0 + 8]; }
        #pragma unroll
        for (int ni = 0; ni < 4; ni++) {
            int c0 = n0 + wn * 32 + ni * 8 + 2 * tg;
            if (tokA >= 0) {
                float y0 = C1_G2 * (float)hh[mi][ni][0] + C2_G2 * (float)mm[mi][ni][0] + C3_G2 * (float)ll[mi][ni][0];
                float y1 = C1_G2 * (float)hh[mi][ni][1] + C2_G2 * (float)mm[mi][ni][1] + C3_G2 * (float)ll[mi][ni][1];
                atomicAdd(&out[(size_t)tokA * D_MODEL + c0],     wA * y0);
                atomicAdd(&out[(size_t)tokA * D_MODEL + c0 + 1], wA * y1);
            }
            if (tokB >= 0) {
                float y2 = C1_G2 * (float)hh[mi][ni][2] + C2_G2 * (float)mm[mi][ni][2] + C3_G2 * (float)ll[mi][ni][2];
                float y3 = C1_G2 * (float)hh[mi][ni][3] + C2_G2 * (float)mm[mi][ni][3] + C3_G2 * (float)ll[mi][ni][3];
                atomicAdd(&out[(size_t)tokB * D_MODEL + c0],     wB * y2);
                atomicAdd(&out[(size_t)tokB * D_MODEL + c0 + 1], wB * y3);
            }
        }
    }
    #undef LOAD2
    #undef CONVERT2
}

// ---------------- aux loss ----------------
__global__ void finalize_kernel(float* __restrict__ out, int out_size) {
    __shared__ float sm[256];
    int tid = threadIdx.x;
    int e = tid & 7, grp = tid >> 3;
    float acc = 0.0f;
    for (int t = grp; t < NTOK; t += 32) acc += g_probs[t * NEXP + e];
    sm[tid] = acc;
    __syncthreads();
    if (tid < NEXP) {
        float P = 0.0f;
        for (int g2 = 0; g2 < 32; g2++) P += sm[tid + 8 * g2];
        float f = (float)g_counts[tid] / (float)(NTOK * 2);
        sm[tid] = f * (P / (float)NTOK);
    }
    __syncthreads();
    if (tid == 0) {
        float aux = 0.0f;
        for (int ee = 0; ee < NEXP; ee++) aux += sm[ee];
        if (out_size > NTOK * D_MODEL)
            out[out_size - 1] = ALPHA * (float)NEXP * aux;
    }
}

// ---------------- launch ----------------
extern "C" void kernel_launch(void* const* d_in, const int* in_sizes, int n_in,
                              void* d_out, int out_size) {
    const float* x  = (const float*)d_in[0];
    const float* Wr = (const float*)d_in[1];
    const float* W1 = (const float*)d_in[2];
    const float* W3 = (const float*)d_in[3];
    const float* W2 = (const float*)d_in[4];
    float* out = (float*)d_out;

    static bool attr_set = false;
    if (!attr_set) {
        cudaFuncSetAttribute(gemm1_kernel, cudaFuncAttributeMaxDynamicSharedMemorySize, SMEM1_BYTES);
        cudaFuncSetAttribute(gemm2_kernel, cudaFuncAttributeMaxDynamicSharedMemorySize, SMEM2_BYTES);
        attr_set = true;
    }

    prep_kernel<<<4096, 256>>>(x, out);
    router_kernel<<<NTOK, 256>>>(x, Wr);
    scan_kernel<<<1, 32>>>();
    scatter_kernel<<<NTOK / 256, 256>>>();

    dim3 g1(NTOK / 128, D_FF / 64, NEXP);      // (16, 64, 8), m fastest
    gemm1_kernel<<<g1, 256, SMEM1_BYTES>>>(W1, W3);

    dim3 g2(NTOK / 128, D_MODEL / 64, NEXP);   // (16, 32, 8), m fastest
    gemm2_kernel<<<g2, 256, SMEM2_BYTES>>>(W2, out);

    finalize_kernel<<<1, 256>>>(out, out_size);
}

// round 11
// speedup vs baseline: 4.4620x; 4.4620x over previous
#include <cuda_runtime.h>
#include <cstdint>

#define D_MODEL 2048
#define D_FF    4096
#define NEXP    8
#define NTOK    2048
#define NPAIR   (NTOK * 2)
#define ALPHA   0.01f

#define BM 128
#define BK 32
#define STAGES 3

// ---------------- scratch (device globals; no runtime allocation) ----------------
__device__ __align__(256) float g_xr[(size_t)NTOK * D_MODEL];   // tf32-rounded x
__device__ __align__(256) float g_H[(size_t)NPAIR * D_FF];      // tf32-rounded hidden
__device__ float g_probs[NTOK * NEXP];
__device__ int   g_sel_e[NTOK * 2];
__device__ float g_sel_w[NTOK * 2];
__device__ int   g_counts[NEXP];
__device__ int   g_offsets[NEXP + 1];
__device__ int   g_cursor[NEXP];
__device__ int   g_pair_token[NPAIR];
__device__ float g_pair_w[NPAIR];

// ---------------- helpers ----------------
__device__ __forceinline__ uint32_t f2tf(float x) {
    uint32_t y;
    asm("cvt.rna.tf32.f32 %0, %1;" : "=r"(y) : "f"(x));
    return y;
}
__device__ __forceinline__ float f2tf_f(float x) { return __uint_as_float(f2tf(x)); }

__device__ __forceinline__ void mma_tf32(float c[4], const uint32_t a[4], const uint32_t b[2]) {
    asm volatile(
        "mma.sync.aligned.m16n8k8.row.col.f32.tf32.tf32.f32 "
        "{%0,%1,%2,%3}, {%4,%5,%6,%7}, {%8,%9}, {%0,%1,%2,%3};"
        : "+f"(c[0]), "+f"(c[1]), "+f"(c[2]), "+f"(c[3])
        : "r"(a[0]), "r"(a[1]), "r"(a[2]), "r"(a[3]), "r"(b[0]), "r"(b[1]));
}

// ldmatrix x4 on 32-bit elements
__device__ __forceinline__ void ldsm4(uint32_t* r, uint32_t addr) {
    asm volatile("ldmatrix.sync.aligned.m8n8.x4.shared.b16 {%0,%1,%2,%3}, [%4];"
                 : "=r"(r[0]), "=r"(r[1]), "=r"(r[2]), "=r"(r[3]) : "r"(addr));
}

__device__ __forceinline__ void cp_async16(uint32_t dst, const void* src, int bytes) {
    asm volatile("cp.async.cg.shared.global [%0], [%1], 16, %2;\n"
                 :: "r"(dst), "l"(src), "r"(bytes));
}
__device__ __forceinline__ void cp_commit() { asm volatile("cp.async.commit_group;\n"); }
template<int N> __device__ __forceinline__ void cp_wait() {
    asm volatile("cp.async.wait_group %0;\n" :: "n"(N));
}

// ---------------- kernel 0: zero output + counts, round x ----------------
__global__ void prep_kernel(const float* __restrict__ x, float* __restrict__ out) {
    int i = blockIdx.x * blockDim.x + threadIdx.x;
    if (i < NEXP) g_counts[i] = 0;
    const float4* x4 = (const float4*)x;
    float4* o4 = (float4*)out;
    float4* r4 = (float4*)g_xr;
    float4 z = make_float4(0.f, 0.f, 0.f, 0.f);
    for (; i < NTOK * D_MODEL / 4; i += gridDim.x * blockDim.x) {
        float4 v = x4[i];
        v.x = f2tf_f(v.x); v.y = f2tf_f(v.y); v.z = f2tf_f(v.z); v.w = f2tf_f(v.w);
        r4[i] = v;
        o4[i] = z;
    }
}

// ---------------- kernel 1: router ----------------
__global__ void router_kernel(const float* __restrict__ x, const float* __restrict__ Wr) {
    int t = blockIdx.x;
    int wid = threadIdx.x >> 5, lane = threadIdx.x & 31;

    const float4* xr = (const float4*)(x + (size_t)t * D_MODEL);
    const float4* wr = (const float4*)(Wr + (size_t)wid * D_MODEL);
    float s = 0.0f;
    for (int i = lane; i < D_MODEL / 4; i += 32) {
        float4 a = xr[i], b = wr[i];
        s += a.x * b.x + a.y * b.y + a.z * b.z + a.w * b.w;
    }
    #pragma unroll
    for (int o = 16; o; o >>= 1) s += __shfl_xor_sync(0xFFFFFFFFu, s, o);

    __shared__ float logits[NEXP];
    if (lane == 0) logits[wid] = s;
    __syncthreads();

    if (threadIdx.x == 0) {
        float mx = -1e30f;
        #pragma unroll
        for (int e = 0; e < NEXP; e++) mx = fmaxf(mx, logits[e]);
        float p[NEXP], sum = 0.0f;
        #pragma unroll
        for (int e = 0; e < NEXP; e++) { p[e] = expf(logits[e] - mx); sum += p[e]; }
        float inv = 1.0f / sum;
        #pragma unroll
        for (int e = 0; e < NEXP; e++) { p[e] *= inv; g_probs[t * NEXP + e] = p[e]; }

        int e0 = 0; float p0 = p[0];
        #pragma unroll
        for (int e = 1; e < NEXP; e++) if (p[e] > p0) { p0 = p[e]; e0 = e; }
        int e1 = -1; float p1 = -1.0f;
        #pragma unroll
        for (int e = 0; e < NEXP; e++) if (e != e0 && p[e] > p1) { p1 = p[e]; e1 = e; }

        float ws = p0 + p1;
        g_sel_e[t * 2 + 0] = e0; g_sel_w[t * 2 + 0] = p0 / ws;
        g_sel_e[t * 2 + 1] = e1; g_sel_w[t * 2 + 1] = p1 / ws;
        atomicAdd(&g_counts[e0], 1);
        atomicAdd(&g_counts[e1], 1);
    }
}

// ---------------- kernel 2: scan ----------------
__global__ void scan_kernel() {
    if (threadIdx.x == 0) {
        int acc = 0;
        g_offsets[0] = 0;
        for (int e = 0; e < NEXP; e++) {
            acc += g_counts[e];
            g_offsets[e + 1] = acc;
            g_cursor[e] = 0;
        }
    }
}

// ---------------- kernel 3: scatter ----------------
__global__ void scatter_kernel() {
    int t = blockIdx.x * blockDim.x + threadIdx.x;
    if (t >= NTOK) return;
    #pragma unroll
    for (int k = 0; k < 2; k++) {
        int e = g_sel_e[t * 2 + k];
        int pos = g_offsets[e] + atomicAdd(&g_cursor[e], 1);
        g_pair_token[pos] = t;
        g_pair_w[pos] = g_sel_w[t * 2 + k];
    }
}

// =======================================================================
// GEMM1: H = silu(xr@W1) * (xr@W3), BM=128 BN=64 BK=32, 3-stage cp.async
// A pre-rounded (g_xr) -> ldmatrix frags, no CVT. B CVT at frag load.
// grid: (m=16, n=64, e=8)  [m fastest => weight-tile L2 reuse]
// =======================================================================
#define G1_BN 64
#define SA_STRIDE 36
#define SB1_STRIDE 72

__global__ void __launch_bounds__(256, 2) gemm1_kernel(
    const float* __restrict__ W1, const float* __restrict__ W3)
{
    extern __shared__ float smem[];
    float* sA_base  = smem;                                   // 3*128*36
    float* sB1_base = smem + STAGES * BM * SA_STRIDE;         // 3*32*72
    float* sB2_base = sB1_base + STAGES * BK * SB1_STRIDE;

    int e = blockIdx.z;
    int seg0 = g_offsets[e], seg1 = g_offsets[e + 1];
    int m_start = seg0 + blockIdx.x * BM;
    if (m_start >= seg1) return;
    int rows = seg1 - m_start;
    if (rows > BM) rows = BM;
    int n0 = blockIdx.y * G1_BN;

    int tid = threadIdx.x;

    // A loader: 128 rows x 8 float4/row = 1024 chunks, 4/thread
    const float* a_src[4];
    uint32_t a_dst_off[4];
    int a_bytes[4];
    #pragma unroll
    for (int j = 0; j < 4; j++) {
        int idx = tid + 256 * j;
        int r = idx >> 3, c4 = idx & 7;
        int tok = (r < rows) ? g_pair_token[m_start + r] : 0;
        a_src[j] = g_xr + (size_t)tok * D_MODEL + c4 * 4;
        a_bytes[j] = (r < rows) ? 16 : 0;
        a_dst_off[j] = (uint32_t)((r * SA_STRIDE + c4 * 4) * 4);
    }
    // B loaders: 32 rows x 16 float4/row = 512 chunks, 2/thread each
    const float *b1_src[2], *b3_src[2];
    uint32_t b_dst_off[2];
    #pragma unroll
    for (int j = 0; j < 2; j++) {
        int idx = tid + 256 * j;
        int r = idx >> 4, c4 = idx & 15;
        size_t base = ((size_t)e * D_MODEL + r) * D_FF + n0 + c4 * 4;
        b1_src[j] = W1 + base;
        b3_src[j] = W3 + base;
        b_dst_off[j] = (uint32_t)((r * SB1_STRIDE + c4 * 4) * 4);
    }

    uint32_t sA_addr  = (uint32_t)__cvta_generic_to_shared(sA_base);
    uint32_t sB1_addr = (uint32_t)__cvta_generic_to_shared(sB1_base);
    uint32_t sB2_addr = (uint32_t)__cvta_generic_to_shared(sB2_base);

    const int KT = D_MODEL / BK;   // 64

    #define G1_LOAD(s, kt) do {                                                   \
        uint32_t aB = sA_addr  + (uint32_t)(s) * (BM * SA_STRIDE * 4);            \
        uint32_t b1B = sB1_addr + (uint32_t)(s) * (BK * SB1_STRIDE * 4);          \
        uint32_t b2B = sB2_addr + (uint32_t)(s) * (BK * SB1_STRIDE * 4);          \
        int koff = (kt) * BK;                                                     \
        _Pragma("unroll")                                                         \
        for (int j = 0; j < 4; j++)                                               \
            cp_async16(aB + a_dst_off[j], a_src[j] + koff, a_bytes[j]);           \
        _Pragma("unroll")                                                         \
        for (int j = 0; j < 2; j++) {                                             \
            cp_async16(b1B + b_dst_off[j], b1_src[j] + (size_t)koff * D_FF, 16);  \
            cp_async16(b2B + b_dst_off[j], b3_src[j] + (size_t)koff * D_FF, 16);  \
        }                                                                         \
    } while (0)

    int wid = tid >> 5, lane = tid & 31;
    int wm = wid & 3, wn = wid >> 2;      // 4 x 2 warp grid; warp tile 32 x 32
    int g = lane >> 2, tg = lane & 3;

    // ldmatrix per-lane row/col selection (x4: tiles by lane>>3)
    int lsel = lane >> 3, lr = lane & 7;
    int lrow_off = (lsel & 1) ? 8 : 0;
    int lcol_off = (lsel & 2) ? 4 : 0;
    uint32_t aoff[2];
    #pragma unroll
    for (int mi = 0; mi < 2; mi++)
        aoff[mi] = (uint32_t)(((wm * 32 + mi * 16 + lr + lrow_off) * SA_STRIDE + lcol_off) * 4);

    float acc1[2][4][4] = {};
    float acc2[2][4][4] = {};

    G1_LOAD(0, 0); cp_commit();
    G1_LOAD(1, 1); cp_commit();

    for (int i = 0; i < KT; i++) {
        int s = i % STAGES;
        if (i + 2 < KT) { G1_LOAD((i + 2) % STAGES, i + 2); cp_commit(); cp_wait<2>(); }
        else if (i + 1 < KT) { cp_wait<1>(); }
        else { cp_wait<0>(); }
        __syncthreads();

        uint32_t aStage = sA_addr + s * (BM * SA_STRIDE * 4);
        const float* pB1 = sB1_base + s * (BK * SB1_STRIDE);
        const float* pB2 = sB2_base + s * (BK * SB1_STRIDE);

        #pragma unroll
        for (int kk = 0; kk < BK; kk += 8) {
            uint32_t a[2][4], b1[4][2], b2[4][2];
            ldsm4(a[0], aStage + aoff[0] + kk * 4);
            ldsm4(a[1], aStage + aoff[1] + kk * 4);
            #pragma unroll
            for (int ni = 0; ni < 4; ni++) {
                int c = wn * 32 + ni * 8 + g;
                b1[ni][0] = f2tf(pB1[(kk + tg) * SB1_STRIDE + c]);
                b1[ni][1] = f2tf(pB1[(kk + tg + 4) * SB1_STRIDE + c]);
                b2[ni][0] = f2tf(pB2[(kk + tg) * SB1_STRIDE + c]);
                b2[ni][1] = f2tf(pB2[(kk + tg + 4) * SB1_STRIDE + c]);
            }
            #pragma unroll
            for (int mi = 0; mi < 2; mi++)
                #pragma unroll
                for (int ni = 0; ni < 4; ni++) {
                    mma_tf32(acc1[mi][ni], a[mi], b1[ni]);
                    mma_tf32(acc2[mi][ni], a[mi], b2[ni]);
                }
        }
        __syncthreads();
    }

    // epilogue: H = round_tf32(silu(gate) * up)  [gemm2 reads H without CVT]
    #pragma unroll
    for (int mi = 0; mi < 2; mi++) {
        int r0 = wm * 32 + mi * 16 + g;
        #pragma unroll
        for (int ni = 0; ni < 4; ni++) {
            int c0 = n0 + wn * 32 + ni * 8 + 2 * tg;
            if (r0 < rows) {
                float* Hr = &g_H[(size_t)(m_start + r0) * D_FF];
                float gv = acc1[mi][ni][0], uv = acc2[mi][ni][0];
                Hr[c0] = f2tf_f(gv * (1.0f / (1.0f + __expf(-gv))) * uv);
                gv = acc1[mi][ni][1]; uv = acc2[mi][ni][1];
                Hr[c0 + 1] = f2tf_f(gv * (1.0f / (1.0f + __expf(-gv))) * uv);
            }
            if (r0 + 8 < rows) {
                float* Hr = &g_H[(size_t)(m_start + r0 + 8) * D_FF];
                float gv = acc1[mi][ni][2], uv = acc2[mi][ni][2];
                Hr[c0] = f2tf_f(gv * (1.0f / (1.0f + __expf(-gv))) * uv);
                gv = acc1[mi][ni][3]; uv = acc2[mi][ni][3];
                Hr[c0 + 1] = f2tf_f(gv * (1.0f / (1.0f + __expf(-gv))) * uv);
            }
        }
    }
    #undef G1_LOAD
}

// =======================================================================
// GEMM2: out += w * (H @ W2), BM=128 BN=128 BK=32, 3-stage cp.async
// A = g_H pre-rounded -> ldmatrix frags, no CVT. B CVT at frag load.
// grid: (m=16, n=16, e=8)
// =======================================================================
#define G2_BN 128
#define SB2_STRIDE 136

__global__ void __launch_bounds__(256, 2) gemm2_kernel(
    const float* __restrict__ W2, float* __restrict__ out)
{
    extern __shared__ float smem[];
    float* sA_base = smem;                                // 3*128*36
    float* sB_base = smem + STAGES * BM * SA_STRIDE;      // 3*32*136

    int e = blockIdx.z;
    int seg0 = g_offsets[e], seg1 = g_offsets[e + 1];
    int m_start = seg0 + blockIdx.x * BM;
    if (m_start >= seg1) return;
    int rows = seg1 - m_start;
    if (rows > BM) rows = BM;
    int n0 = blockIdx.y * G2_BN;

    int tid = threadIdx.x;

    const float* a_src[4];
    uint32_t a_dst_off[4];
    int a_bytes[4];
    #pragma unroll
    for (int j = 0; j < 4; j++) {
        int idx = tid + 256 * j;
        int r = idx >> 3, c4 = idx & 7;
        a_src[j] = &g_H[(size_t)(m_start + (r < rows ? r : 0)) * D_FF + c4 * 4];
        a_bytes[j] = (r < rows) ? 16 : 0;
        a_dst_off[j] = (uint32_t)((r * SA_STRIDE + c4 * 4) * 4);
    }
    // B loader: 32 rows x 32 float4/row = 1024 chunks, 4/thread
    const float* b_src[4];
    uint32_t b_dst_off[4];
    #pragma unroll
    for (int j = 0; j < 4; j++) {
        int idx = tid + 256 * j;
        int r = idx >> 5, c4 = idx & 31;
        b_src[j] = W2 + ((size_t)e * D_FF + r) * D_MODEL + n0 + c4 * 4;
        b_dst_off[j] = (uint32_t)((r * SB2_STRIDE + c4 * 4) * 4);
    }

    uint32_t sA_addr = (uint32_t)__cvta_generic_to_shared(sA_base);
    uint32_t sB_addr = (uint32_t)__cvta_generic_to_shared(sB_base);

    const int KT = D_FF / BK;  // 128

    #define G2_LOAD(s, kt) do {                                                  \
        uint32_t aB = sA_addr + (uint32_t)(s) * (BM * SA_STRIDE * 4);             \
        uint32_t bB = sB_addr + (uint32_t)(s) * (BK * SB2_STRIDE * 4);            \
        int koff = (kt) * BK;                                                     \
        _Pragma("unroll")                                                         \
        for (int j = 0; j < 4; j++)                                               \
            cp_async16(aB + a_dst_off[j], a_src[j] + koff, a_bytes[j]);           \
        _Pragma("unroll")                                                         \
        for (int j = 0; j < 4; j++)                                               \
            cp_async16(bB + b_dst_off[j], b_src[j] + (size_t)koff * D_MODEL, 16); \
    } while (0)

    int wid = tid >> 5, lane = tid & 31;
    int wm = wid & 3, wn = wid >> 2;      // 4 x 2; warp tile 32 x 64
    int g = lane >> 2, tg = lane & 3;

    int lsel = lane >> 3, lr = lane & 7;
    int lrow_off = (lsel & 1) ? 8 : 0;
    int lcol_off = (lsel & 2) ? 4 : 0;
    uint32_t aoff[2];
    #pragma unroll
    for (int mi = 0; mi < 2; mi++)
        aoff[mi] = (uint32_t)(((wm * 32 + mi * 16 + lr + lrow_off) * SA_STRIDE + lcol_off) * 4);

    float acc[2][8][4] = {};

    G2_LOAD(0, 0); cp_commit();
    G2_LOAD(1, 1); cp_commit();

    for (int i = 0; i < KT; i++) {
        int s = i % STAGES;
        if (i + 2 < KT) { G2_LOAD((i + 2) % STAGES, i + 2); cp_commit(); cp_wait<2>(); }
        else if (i + 1 < KT) { cp_wait<1>(); }
        else { cp_wait<0>(); }
        __syncthreads();

        uint32_t aStage = sA_addr + s * (BM * SA_STRIDE * 4);
        const float* pB = sB_base + s * (BK * SB2_STRIDE);

        #pragma unroll
        for (int kk = 0; kk < BK; kk += 8) {
            uint32_t a[2][4], b[8][2];
            ldsm4(a[0], aStage + aoff[0] + kk * 4);
            ldsm4(a[1], aStage + aoff[1] + kk * 4);
            #pragma unroll
            for (int ni = 0; ni < 8; ni++) {
                int c = wn * 64 + ni * 8 + g;
                b[ni][0] = f2tf(pB[(kk + tg) * SB2_STRIDE + c]);
                b[ni][1] = f2tf(pB[(kk + tg + 4) * SB2_STRIDE + c]);
            }
            #pragma unroll
            for (int mi = 0; mi < 2; mi++)
                #pragma unroll
                for (int ni = 0; ni < 8; ni++)
                    mma_tf32(acc[mi][ni], a[mi], b[ni]);
        }
        __syncthreads();
    }

    // epilogue: weighted atomic scatter-add (exactly 2 adds per out element -> deterministic)
    #pragma unroll
    for (int mi = 0; mi < 2; mi++) {
        int r0 = wm * 32 + mi * 16 + g;
        int tokA = -1, tokB = -1;
        float wA = 0.f, wB = 0.f;
        if (r0 < rows)     { tokA = g_pair_token[m_start + r0];     wA = g_pair_w[m_start + r0]; }
        if (r0 + 8 < rows) { tokB = g_pair_token[m_start + r0 + 8]; wB = g_pair_w[m_start + r0 + 8]; }
        #pragma unroll
        for (int ni = 0; ni < 8; ni++) {
            int c0 = n0 + wn * 64 + ni * 8 + 2 * tg;
            if (tokA >= 0) {
                atomicAdd(&out[(size_t)tokA * D_MODEL + c0],     wA * acc[mi][ni][0]);
                atomicAdd(&out[(size_t)tokA * D_MODEL + c0 + 1], wA * acc[mi][ni][1]);
            }
            if (tokB >= 0) {
                atomicAdd(&out[(size_t)tokB * D_MODEL + c0],     wB * acc[mi][ni][2]);
                atomicAdd(&out[(size_t)tokB * D_MODEL + c0 + 1], wB * acc[mi][ni][3]);
            }
        }
    }
    #undef G2_LOAD
}

// ---------------- kernel 6: aux loss ----------------
__global__ void finalize_kernel(float* __restrict__ out, int out_size) {
    __shared__ float sm[256];
    int tid = threadIdx.x;
    int e = tid & 7;
    int grp = tid >> 3;
    float acc = 0.0f;
    for (int t = grp; t < NTOK; t += 32) acc += g_probs[t * NEXP + e];
    sm[tid] = acc;
    __syncthreads();
    if (tid < NEXP) {
        float P = 0.0f;
        for (int g2 = 0; g2 < 32; g2++) P += sm[tid + 8 * g2];
        float f = (float)g_counts[tid] / (float)(NTOK * 2);
        sm[tid] = f * (P / (float)NTOK);
    }
    __syncthreads();
    if (tid == 0) {
        float aux = 0.0f;
        for (int ee = 0; ee < NEXP; ee++) aux += sm[ee];
        if (out_size > NTOK * D_MODEL)
            out[out_size - 1] = ALPHA * (float)NEXP * aux;
    }
}

// ---------------- launch ----------------
extern "C" void kernel_launch(void* const* d_in, const int* in_sizes, int n_in,
                              void* d_out, int out_size) {
    const float* x  = (const float*)d_in[0];
    const float* Wr = (const float*)d_in[1];
    const float* W1 = (const float*)d_in[2];
    const float* W3 = (const float*)d_in[3];
    const float* W2 = (const float*)d_in[4];
    float* out = (float*)d_out;

    const int SMEM1 = STAGES * (BM * SA_STRIDE + 2 * BK * SB1_STRIDE) * 4;   // 110592
    const int SMEM2 = STAGES * (BM * SA_STRIDE + BK * SB2_STRIDE) * 4;       // 107520

    static bool attr_set = false;
    if (!attr_set) {
        cudaFuncSetAttribute(gemm1_kernel, cudaFuncAttributeMaxDynamicSharedMemorySize, SMEM1);
        cudaFuncSetAttribute(gemm2_kernel, cudaFuncAttributeMaxDynamicSharedMemorySize, SMEM2);
        attr_set = true;
    }

    prep_kernel<<<4096, 256>>>(x, out);
    router_kernel<<<NTOK, 256>>>(x, Wr);
    scan_kernel<<<1, 32>>>();
    scatter_kernel<<<NTOK / 256, 256>>>();

    dim3 g1(NTOK / BM, D_FF / G1_BN, NEXP);     // (16, 64, 8), m fastest
    gemm1_kernel<<<g1, 256, SMEM1>>>(W1, W3);

    dim3 g2(NTOK / BM, D_MODEL / G2_BN, NEXP);  // (16, 16, 8), m fastest
    gemm2_kernel<<<g2, 256, SMEM2>>>(W2, out);

    finalize_kernel<<<1, 256>>>(out, out_size);
}